// round 7
// baseline (speedup 1.0000x reference)
#include <cuda_runtime.h>
#include <cuda_bf16.h>

// NCEAverage: B=256, D=128, N=1e6, K1=2048, T=0.07, MOMENTUM=0.5
// Output: [ out_l(B*K1) | out_ab(B*K1) | new_memory_l(N*D) | new_memory_ab(N*D) ]
//
// Strategy: bucketed row->task lists (memset + 1 scatter kernel, no scan),
// then ONE streaming pass that copies BOTH banks and computes BOTH dot
// products for every task as the rows stream through registers.

#define DIM      128
#define T_INV    (1.0f / 0.07f)
#define N_MAX    1048576
#define BK_MAX   524288
#define CAP      12

__device__ int g_count[N_MAX];
__device__ int g_tasks[N_MAX * CAP];
__device__ int g_ovf  [4096];
__device__ int g_novf;

// ---------------- bucket scatter ----------------
__global__ void k_scatter(const int* __restrict__ idx, int bk) {
    for (int t = blockIdx.x * blockDim.x + threadIdx.x; t < bk;
         t += gridDim.x * blockDim.x) {
        const int row  = idx[t];
        const int slot = atomicAdd(&g_count[row], 1);
        if (slot < CAP) g_tasks[row * CAP + slot] = t;
        else            g_ovf[atomicAdd(&g_novf, 1)] = t;
    }
}

// ---------------- fused dual-bank copy + score streaming pass ---------------
// One warp per row: copy both 512B rows, then for each task on the row
// compute dot(mem_l[r], ab[b]) and dot(mem_ab[r], l[b]).
__global__ void __launch_bounds__(256) stream_score(
    const float4* __restrict__ bank_l, const float4* __restrict__ bank_ab,
    float4* __restrict__ out_ml, float4* __restrict__ out_mab,
    const float4* __restrict__ ql, const float4* __restrict__ qab,
    float* __restrict__ out_l, float* __restrict__ out_ab,
    int Nrows, int K1)
{
    const int lane = threadIdx.x & 31;
    const int nw   = gridDim.x * (blockDim.x >> 5);
    int r          = blockIdx.x * (blockDim.x >> 5) + (threadIdx.x >> 5);

    if (r >= Nrows) return;
    float4 vl  = __ldcs(&bank_l [(long long)r * 32 + lane]);
    float4 vab = __ldcs(&bank_ab[(long long)r * 32 + lane]);

    while (true) {
        const int rn = r + nw;
        float4 nl, nab;
        if (rn < Nrows) {                       // prefetch next row, both banks
            nl  = __ldcs(&bank_l [(long long)rn * 32 + lane]);
            nab = __ldcs(&bank_ab[(long long)rn * 32 + lane]);
        }

        __stcs(&out_ml [(long long)r * 32 + lane], vl);
        __stcs(&out_mab[(long long)r * 32 + lane], vab);

        int cnt = g_count[r];
        if (cnt) {
            if (cnt > CAP) cnt = CAP;
            const int base = r * CAP;
            for (int j = 0; j < cnt; ++j) {
                const int task = g_tasks[base + j];
                const int b    = task / K1;
                const float4 q1 = qab[b * 32 + lane];   // vs bank_l
                const float4 q2 = ql [b * 32 + lane];   // vs bank_ab
                float s1 = vl.x * q1.x + vl.y * q1.y + vl.z * q1.z + vl.w * q1.w;
                float s2 = vab.x * q2.x + vab.y * q2.y + vab.z * q2.z + vab.w * q2.w;
                #pragma unroll
                for (int o = 16; o; o >>= 1) {
                    s1 += __shfl_xor_sync(0xffffffffu, s1, o);
                    s2 += __shfl_xor_sync(0xffffffffu, s2, o);
                }
                if (lane == 0) {
                    out_ab[task] = s1 * T_INV;
                    out_l [task] = s2 * T_INV;
                }
            }
        }
        if (rn >= Nrows) break;
        r  = rn;
        vl = nl;
        vab = nab;
    }
}

// ---------------- overflow fixup (expected: zero tasks) ----------------
__global__ void __launch_bounds__(256) k_overflow(
    const float* __restrict__ mem_l, const float* __restrict__ mem_ab,
    const float4* __restrict__ ql, const float4* __restrict__ qab,
    const int* __restrict__ idx,
    float* __restrict__ out_l, float* __restrict__ out_ab, int K1)
{
    const int n = g_novf;
    const int lane = threadIdx.x & 31;
    for (int i = threadIdx.x >> 5; i < n; i += 8) {
        const int task = g_ovf[i];
        const int b    = task / K1;
        const long long row = idx[task];
        const float4 wl  = ((const float4*)(mem_l  + row * DIM))[lane];
        const float4 wab = ((const float4*)(mem_ab + row * DIM))[lane];
        const float4 q1  = qab[b * 32 + lane];
        const float4 q2  = ql [b * 32 + lane];
        float s1 = wl.x * q1.x + wl.y * q1.y + wl.z * q1.z + wl.w * q1.w;
        float s2 = wab.x * q2.x + wab.y * q2.y + wab.z * q2.z + wab.w * q2.w;
        #pragma unroll
        for (int o = 16; o; o >>= 1) {
            s1 += __shfl_xor_sync(0xffffffffu, s1, o);
            s2 += __shfl_xor_sync(0xffffffffu, s2, o);
        }
        if (lane == 0) {
            out_ab[task] = s1 * T_INV;
            out_l [task] = s2 * T_INV;
        }
    }
}

// ---------------- EMA + normalize + scatter (last-occurrence wins) ----------
__global__ void __launch_bounds__(DIM) update_kernel(
    const float* __restrict__ l, const float* __restrict__ ab,
    const int* __restrict__ y,
    const float* __restrict__ mem_l, const float* __restrict__ mem_ab,
    float* __restrict__ out_ml, float* __restrict__ out_mab, int B)
{
    const int b   = blockIdx.x;
    const int tid = threadIdx.x;

    __shared__ int skip;
    __shared__ int yy_s;
    if (tid == 0) { skip = 0; yy_s = y[b]; }
    __syncthreads();
    const int yy = yy_s;
    for (int j = b + 1 + tid; j < B; j += DIM)
        if (y[j] == yy) skip = 1;     // benign race
    __syncthreads();
    if (skip) return;

    const long long r = yy;
    const float vl  = 0.5f * mem_l [r * DIM + tid] + 0.5f * l [b * DIM + tid];
    const float vab = 0.5f * mem_ab[r * DIM + tid] + 0.5f * ab[b * DIM + tid];

    float sl = vl * vl, sab = vab * vab;
    #pragma unroll
    for (int off = 16; off; off >>= 1) {
        sl  += __shfl_xor_sync(0xffffffffu, sl,  off);
        sab += __shfl_xor_sync(0xffffffffu, sab, off);
    }
    __shared__ float wsl[4], wsab[4];
    const int w = tid >> 5, lane = tid & 31;
    if (lane == 0) { wsl[w] = sl; wsab[w] = sab; }
    __syncthreads();
    const float tsl  = wsl[0]  + wsl[1]  + wsl[2]  + wsl[3];
    const float tsab = wsab[0] + wsab[1] + wsab[2] + wsab[3];

    out_ml [r * DIM + tid] = vl  * rsqrtf(tsl);
    out_mab[r * DIM + tid] = vab * rsqrtf(tsab);
}

extern "C" void kernel_launch(void* const* d_in, const int* in_sizes, int n_in,
                              void* d_out, int out_size)
{
    const float* l      = (const float*)d_in[0];
    const float* ab     = (const float*)d_in[1];
    const int*   y      = (const int*)  d_in[2];
    const int*   idx    = (const int*)  d_in[3];
    const float* mem_l  = (const float*)d_in[4];
    const float* mem_ab = (const float*)d_in[5];

    const int       B     = in_sizes[2];
    const int       BK    = in_sizes[3];
    const int       K1    = BK / B;
    const long long ND    = (long long)in_sizes[4];
    const int       Nrows = (int)(ND / DIM);

    float* out = (float*)d_out;
    float* out_l   = out;
    float* out_ab  = out + BK;
    float* out_ml  = out + 2LL * BK;
    float* out_mab = out + 2LL * BK + ND;

    // ---- reset counters (graph-capturable, no allocation) ----
    void* p_count; cudaGetSymbolAddress(&p_count, g_count);
    void* p_novf;  cudaGetSymbolAddress(&p_novf,  g_novf);
    cudaMemsetAsync(p_count, 0, (size_t)Nrows * sizeof(int));
    cudaMemsetAsync(p_novf,  0, sizeof(int));

    // ---- bucket scatter: row -> task list ----
    k_scatter<<<512, 1024>>>(idx, BK);

    // ---- fused single pass: copy both banks + all scores ----
    stream_score<<<148 * 8, 256>>>((const float4*)mem_l, (const float4*)mem_ab,
                                   (float4*)out_ml, (float4*)out_mab,
                                   (const float4*)l, (const float4*)ab,
                                   out_l, out_ab, Nrows, K1);

    // ---- overflow tasks (expected none) ----
    k_overflow<<<1, 256>>>(mem_l, mem_ab, (const float4*)l, (const float4*)ab,
                           idx, out_l, out_ab, K1);

    // ---- row updates (after the copy; reads OLD memory from inputs) ----
    update_kernel<<<B, DIM>>>(l, ab, y, mem_l, mem_ab, out_ml, out_mab, B);
}